// round 10
// baseline (speedup 1.0000x reference)
#include <cuda_runtime.h>
#include <cuda_bf16.h>

// ---------------------------------------------------------------------------
// ConvLinearAttention fused pipeline, fp32 + packed f32x2 FFMA GEMMs.
//   B=16, C=256, H*W=4096, HEADS=4, DIM_HEAD=32, inner=128
// Pipeline (7 launches):
//   K1: qkv = w_qkv @ x            (GEMM, per batch [384x256]@[256x4096])
//   K2: fused: q softmax over d * SCALE (blocks 0..1023)
//            + k row stats max/1/sum(exp) (blocks 1024..3071)
//   K3: partial context  ctx[d,e] += exp(k[d,n]-max_d) * v[e,n]   (chunked n)
//   K4: fused: reduce ctx chunks (apply 1/sum_d) in smem, then
//       Wf[b][o][h*32+d] = sum_e w_out[o][h*32+e] * ctx[b][h][d][e]
//       (folds context^T @ q into the output projection weight)
//   K5: out = Wf[b] @ q + b_out    (GEMM [256x128]@[128x4096]) + per-tile
//       sum/sumsq partials for the per-sample norm
//   K6: finalize mean / rstd per batch
//   K7: out = (out - mean)*rstd*gamma[c] + beta[c]   (in place on d_out)
// GEMM: double-buffered smem (one barrier per k-tile) + register prefetch
// of the next k-tile, so LDG latency and STS drain overlap FFMA2 work.
// ---------------------------------------------------------------------------

#define BATCH   16
#define CHAN    256
#define NPIX    4096
#define O3      384
#define INNER   128
#define HEADS   4
#define DHEAD   32
#define SCALE_Q 0.17677669529663687f   // 32^-0.5
#define EPS_GN  1e-5f

typedef unsigned long long ULL;

// ---- scratch (device globals: allocation-free) ----------------------------
__device__ float g_qkv[BATCH * O3 * NPIX];          // 96 MB
__device__ float g_kmax[BATCH * HEADS * DHEAD];     // 2048
__device__ float g_kinv[BATCH * HEADS * DHEAD];     // 2048
__device__ float g_ctx_part[32 * 64 * 1024];        // 8 MB  [chunk][bh][d*32+e]
__device__ float g_wf[BATCH * CHAN * INNER];        // 2 MB
__device__ float g_statpart[BATCH * 64 * 2];        // per-tile {sum, sumsq}
__device__ float g_meanrstd[BATCH * 2];             // {mean, rstd}

// ---- packed f32x2 helpers --------------------------------------------------
__device__ __forceinline__ ULL pack2(float x) {
    ULL r;
    asm("mov.b64 %0, {%1, %1};" : "=l"(r) : "f"(x));
    return r;
}
__device__ __forceinline__ void ffma2(ULL& d, ULL a, ULL b, ULL c) {
    asm("fma.rn.f32x2 %0, %1, %2, %3;" : "=l"(d) : "l"(a), "l"(b), "l"(c));
}
__device__ __forceinline__ float2 unpack2(ULL v) {
    float2 f;
    asm("mov.b64 {%0, %1}, %2;" : "=f"(f.x), "=f"(f.y) : "l"(v));
    return f;
}

// ---------------------------------------------------------------------------
// Tiled GEMM: C[b] = A[b] (MxK) @ Bm[b] (KxN), 128x128 tile, BK=16,
// 256 threads, 8m x (4+4)n per thread, packed fma.rn.f32x2 accumulation.
// Thread n-columns: n0 + tx*4 + {0..3} and n0 + 64 + tx*4 + {0..3}
//   -> conflict-free LDS.128 on the B fragment, coalesced epilogue stores.
// Double-buffered smem: one __syncthreads per k-tile.
// FUSE: adds bias[row] and emits per-tile sum/sumsq partials.
// ---------------------------------------------------------------------------
template <bool FUSE>
__global__ __launch_bounds__(256, 2)
void gemm_f32x2_kernel(const float* __restrict__ A,
                       const float* __restrict__ Bm,
                       float* __restrict__ Cm,
                       int K, int lda, int ldb, int ldc,
                       long aStride, long bStride, long cStride,
                       const float* __restrict__ bias,
                       float* __restrict__ statPart,
                       int tilesPerBatch)
{
    __shared__ float As[2][16][132];   // [buf][k][m], padded
    __shared__ float Bs[2][16][128];   // [buf][k][n]

    const int b  = blockIdx.z;
    const float* Ab = A  + (long)b * aStride;
    const float* Bb = Bm + (long)b * bStride;
    float*       Cb = Cm + (long)b * cStride;

    const int m0  = blockIdx.y * 128;
    const int n0  = blockIdx.x * 128;
    const int tid = threadIdx.x;
    const int tx  = tid & 15;        // n-tile coord
    const int ty  = tid >> 4;        // m-tile coord

    ULL acc[8][4];
#pragma unroll
    for (int i = 0; i < 8; i++)
#pragma unroll
        for (int j = 0; j < 4; j++) acc[i][j] = 0ull;

    const int ar = tid >> 2;          // 0..63
    const int ac = (tid & 3) * 4;     // 0,4,8,12
    const int bk = tid >> 5;          // 0..7
    const int bn = (tid & 31) * 4;    // 0..124

    const float* aPtr0 = Ab + (long)(m0 + ar)      * lda + ac;
    const float* aPtr1 = Ab + (long)(m0 + ar + 64) * lda + ac;
    const float* bPtr0 = Bb + (long)bk       * ldb + n0 + bn;
    const float* bPtr1 = Bb + (long)(bk + 8) * ldb + n0 + bn;

    // prologue: tile 0 -> buf 0
    float4 av0 = *(const float4*)(aPtr0);
    float4 av1 = *(const float4*)(aPtr1);
    float4 bv0 = *(const float4*)(bPtr0);
    float4 bv1 = *(const float4*)(bPtr1);
    As[0][ac + 0][ar]      = av0.x;  As[0][ac + 1][ar]      = av0.y;
    As[0][ac + 2][ar]      = av0.z;  As[0][ac + 3][ar]      = av0.w;
    As[0][ac + 0][ar + 64] = av1.x;  As[0][ac + 1][ar + 64] = av1.y;
    As[0][ac + 2][ar + 64] = av1.z;  As[0][ac + 3][ar + 64] = av1.w;
    *(float4*)&Bs[0][bk][bn]     = bv0;
    *(float4*)&Bs[0][bk + 8][bn] = bv1;

    // prefetch tile 1 into registers
    if (16 < K) {
        av0 = *(const float4*)(aPtr0 + 16);
        av1 = *(const float4*)(aPtr1 + 16);
        bv0 = *(const float4*)(bPtr0 + (long)16 * ldb);
        bv1 = *(const float4*)(bPtr1 + (long)16 * ldb);
    }
    __syncthreads();

    int buf = 0;
    for (int k0 = 0; k0 < K; k0 += 16) {
#pragma unroll
        for (int k = 0; k < 16; k++) {
            const float4 a0 = *(const float4*)&As[buf][k][ty * 8];
            const float4 a1 = *(const float4*)&As[buf][k][ty * 8 + 4];
            // conflict-free: quarter-warp phase reads consecutive float4s
            const ulonglong2 bq0 = *(const ulonglong2*)&Bs[buf][k][tx * 4];      // n: tx*4+{0..3}
            const ulonglong2 bq1 = *(const ulonglong2*)&Bs[buf][k][64 + tx * 4]; // n: 64+tx*4+{0..3}
            ULL ap;
            ap = pack2(a0.x);
            ffma2(acc[0][0], ap, bq0.x, acc[0][0]);
            ffma2(acc[0][1], ap, bq0.y, acc[0][1]);
            ffma2(acc[0][2], ap, bq1.x, acc[0][2]);
            ffma2(acc[0][3], ap, bq1.y, acc[0][3]);
            ap = pack2(a0.y);
            ffma2(acc[1][0], ap, bq0.x, acc[1][0]);
            ffma2(acc[1][1], ap, bq0.y, acc[1][1]);
            ffma2(acc[1][2], ap, bq1.x, acc[1][2]);
            ffma2(acc[1][3], ap, bq1.y, acc[1][3]);
            ap = pack2(a0.z);
            ffma2(acc[2][0], ap, bq0.x, acc[2][0]);
            ffma2(acc[2][1], ap, bq0.y, acc[2][1]);
            ffma2(acc[2][2], ap, bq1.x, acc[2][2]);
            ffma2(acc[2][3], ap, bq1.y, acc[2][3]);
            ap = pack2(a0.w);
            ffma2(acc[3][0], ap, bq0.x, acc[3][0]);
            ffma2(acc[3][1], ap, bq0.y, acc[3][1]);
            ffma2(acc[3][2], ap, bq1.x, acc[3][2]);
            ffma2(acc[3][3], ap, bq1.y, acc[3][3]);
            ap = pack2(a1.x);
            ffma2(acc[4][0], ap, bq0.x, acc[4][0]);
            ffma2(acc[4][1], ap, bq0.y, acc[4][1]);
            ffma2(acc[4][2], ap, bq1.x, acc[4][2]);
            ffma2(acc[4][3], ap, bq1.y, acc[4][3]);
            ap = pack2(a1.y);
            ffma2(acc[5][0], ap, bq0.x, acc[5][0]);
            ffma2(acc[5][1], ap, bq0.y, acc[5][1]);
            ffma2(acc[5][2], ap, bq1.x, acc[5][2]);
            ffma2(acc[5][3], ap, bq1.y, acc[5][3]);
            ap = pack2(a1.z);
            ffma2(acc[6][0], ap, bq0.x, acc[6][0]);
            ffma2(acc[6][1], ap, bq0.y, acc[6][1]);
            ffma2(acc[6][2], ap, bq1.x, acc[6][2]);
            ffma2(acc[6][3], ap, bq1.y, acc[6][3]);
            ap = pack2(a1.w);
            ffma2(acc[7][0], ap, bq0.x, acc[7][0]);
            ffma2(acc[7][1], ap, bq0.y, acc[7][1]);
            ffma2(acc[7][2], ap, bq1.x, acc[7][2]);
            ffma2(acc[7][3], ap, bq1.y, acc[7][3]);
        }

        if (k0 + 16 < K) {
            // store prefetched tile k0+16 into the other buffer
            const int nb = buf ^ 1;
            As[nb][ac + 0][ar]      = av0.x;  As[nb][ac + 1][ar]      = av0.y;
            As[nb][ac + 2][ar]      = av0.z;  As[nb][ac + 3][ar]      = av0.w;
            As[nb][ac + 0][ar + 64] = av1.x;  As[nb][ac + 1][ar + 64] = av1.y;
            As[nb][ac + 2][ar + 64] = av1.z;  As[nb][ac + 3][ar + 64] = av1.w;
            *(float4*)&Bs[nb][bk][bn]     = bv0;
            *(float4*)&Bs[nb][bk + 8][bn] = bv1;
            __syncthreads();
            buf = nb;
            // prefetch tile k0+32 into registers (overlaps next compute)
            if (k0 + 32 < K) {
                av0 = *(const float4*)(aPtr0 + k0 + 32);
                av1 = *(const float4*)(aPtr1 + k0 + 32);
                bv0 = *(const float4*)(bPtr0 + (long)(k0 + 32) * ldb);
                bv1 = *(const float4*)(bPtr1 + (long)(k0 + 32) * ldb);
            }
        }
    }

    // ---- epilogue -----------------------------------------------------------
    float lsum = 0.f, lsq = 0.f;
#pragma unroll
    for (int i = 0; i < 8; i++) {
        const int row = m0 + ty * 8 + i;
        float bv = 0.f;
        if (FUSE) bv = bias[row];
        float out[8];
        float2 p;
        p = unpack2(acc[i][0]); out[0] = p.x + bv; out[1] = p.y + bv;
        p = unpack2(acc[i][1]); out[2] = p.x + bv; out[3] = p.y + bv;
        p = unpack2(acc[i][2]); out[4] = p.x + bv; out[5] = p.y + bv;
        p = unpack2(acc[i][3]); out[6] = p.x + bv; out[7] = p.y + bv;
        if (FUSE) {
#pragma unroll
            for (int j = 0; j < 8; j++) { lsum += out[j]; lsq += out[j] * out[j]; }
        }
        float* crow = Cb + (long)row * ldc + n0;
        *(float4*)(crow + tx * 4)      = make_float4(out[0], out[1], out[2], out[3]);
        *(float4*)(crow + 64 + tx * 4) = make_float4(out[4], out[5], out[6], out[7]);
    }

    if (FUSE) {
        float* rs = &As[0][0][0];  // reuse smem: 512 floats
        __syncthreads();           // all compute reads of smem done
        rs[tid]       = lsum;
        rs[256 + tid] = lsq;
        __syncthreads();
#pragma unroll
        for (int s = 128; s > 0; s >>= 1) {
            if (tid < s) {
                rs[tid]       += rs[tid + s];
                rs[256 + tid] += rs[256 + tid + s];
            }
            __syncthreads();
        }
        if (tid == 0) {
            const int tileIdx = blockIdx.y * gridDim.x + blockIdx.x;
            statPart[((long)b * tilesPerBatch + tileIdx) * 2 + 0] = rs[0];
            statPart[((long)b * tilesPerBatch + tileIdx) * 2 + 1] = rs[256];
        }
    }
}

// ---------------------------------------------------------------------------
// K2 (fused): blocks 0..1023  -> q softmax over d (*SCALE), in place.
//             blocks 1024..3071 -> k row stats: max over n, 1/sum(exp(k-max)).
// Disjoint slices of g_qkv; one launch overlaps the latency-bound q-softmax
// with the bandwidth-bound k reduction.
// ---------------------------------------------------------------------------
__global__ __launch_bounds__(256)
void qsm_kstats_kernel()
{
    __shared__ float sm[256];
    const int tid = threadIdx.x;

    if (blockIdx.x < 1024) {
        // ---- q softmax: one thread per (b,h,n) ----
        const int idx = blockIdx.x * 256 + tid;                  // 0 .. 262143
        const int n  = idx & (NPIX - 1);
        const int bh = idx >> 12;                                // 0..63
        const int b  = bh >> 2;
        const int h  = bh & 3;
        float* base = g_qkv + ((long)b * O3 + h * DHEAD) * NPIX + n;

        float v[DHEAD];
        float mx = -3.0e38f;
#pragma unroll
        for (int d = 0; d < DHEAD; d++) {
            v[d] = base[(long)d * NPIX];
            mx = fmaxf(mx, v[d]);
        }
        float s = 0.f;
#pragma unroll
        for (int d = 0; d < DHEAD; d++) {
            v[d] = __expf(v[d] - mx);
            s += v[d];
        }
        const float inv = SCALE_Q / s;
#pragma unroll
        for (int d = 0; d < DHEAD; d++) base[(long)d * NPIX] = v[d] * inv;
    } else {
        // ---- k stats: one block per (b,hd) row ----
        const int row = blockIdx.x - 1024;          // b*128 + hd
        const int b   = row >> 7;
        const int hd  = row & 127;
        const float* p = g_qkv + ((long)b * O3 + INNER + hd) * NPIX;

        float mx = -3.0e38f;
#pragma unroll 4
        for (int i = tid * 4; i < NPIX; i += 256 * 4) {
            const float4 v = *(const float4*)(p + i);
            mx = fmaxf(mx, fmaxf(fmaxf(v.x, v.y), fmaxf(v.z, v.w)));
        }
        sm[tid] = mx;
        __syncthreads();
        for (int s = 128; s > 0; s >>= 1) {
            if (tid < s) sm[tid] = fmaxf(sm[tid], sm[tid + s]);
            __syncthreads();
        }
        mx = sm[0];
        __syncthreads();

        float acc = 0.f;
#pragma unroll 4
        for (int i = tid * 4; i < NPIX; i += 256 * 4) {
            const float4 v = *(const float4*)(p + i);
            acc += __expf(v.x - mx) + __expf(v.y - mx) + __expf(v.z - mx) + __expf(v.w - mx);
        }
        sm[tid] = acc;
        __syncthreads();
        for (int s = 128; s > 0; s >>= 1) {
            if (tid < s) sm[tid] += sm[tid + s];
            __syncthreads();
        }
        if (tid == 0) {
            g_kmax[row] = mx;
            g_kinv[row] = 1.0f / sm[0];
        }
    }
}

// ---------------------------------------------------------------------------
// K3: partial context. grid = (chunk=32, bh=64), 128 threads.
// Each block: n-chunk of 128 columns; stages exp(k - max) and v transposed
// in smem; thread (d = tid&31, eb = (tid>>5)*8) accumulates 8 ctx entries.
// ---------------------------------------------------------------------------
__global__ __launch_bounds__(128)
void ctx_part_kernel()
{
    __shared__ float keT[128][33];
    __shared__ float vsT[128][33];

    const int chunk = blockIdx.x;      // 0..31
    const int bh    = blockIdx.y;      // 0..63
    const int b = bh >> 2, h = bh & 3;
    const int nbase = chunk * 128;
    const float* kbase = g_qkv + ((long)b * O3 + INNER     + h * DHEAD) * NPIX + nbase;
    const float* vbase = g_qkv + ((long)b * O3 + 2 * INNER + h * DHEAD) * NPIX + nbase;
    const int tid = threadIdx.x;

#pragma unroll
    for (int i = 0; i < 8; i++) {
        const int idx = tid + i * 128;
        const int r  = idx >> 5;             // 0..31 (d/e row)
        const int c  = (idx & 31) * 4;       // 0..124
        const float mx = g_kmax[bh * DHEAD + r];
        const float4 kv = *(const float4*)(kbase + (long)r * NPIX + c);
        keT[c + 0][r] = __expf(kv.x - mx);
        keT[c + 1][r] = __expf(kv.y - mx);
        keT[c + 2][r] = __expf(kv.z - mx);
        keT[c + 3][r] = __expf(kv.w - mx);
        const float4 vv = *(const float4*)(vbase + (long)r * NPIX + c);
        vsT[c + 0][r] = vv.x;
        vsT[c + 1][r] = vv.y;
        vsT[c + 2][r] = vv.z;
        vsT[c + 3][r] = vv.w;
    }
    __syncthreads();

    const int d  = tid & 31;
    const int eb = (tid >> 5) * 8;
    float acc[8] = {0, 0, 0, 0, 0, 0, 0, 0};
#pragma unroll 4
    for (int n = 0; n < 128; n++) {
        const float kd = keT[n][d];
#pragma unroll
        for (int i = 0; i < 8; i++) acc[i] += kd * vsT[n][eb + i];
    }
    float* out = g_ctx_part + ((long)chunk * 64 + bh) * 1024 + d * 32 + eb;
#pragma unroll
    for (int i = 0; i < 8; i++) out[i] = acc[i];
}

// ---------------------------------------------------------------------------
// K4 (fused): per (b,h) block (64 blocks, 256 threads):
//   stage 1: reduce g_ctx_part over 32 chunks into smem ctx[32][33],
//            applying 1/sum_d;
//   stage 2: Wf[b][o][h*32+d] = sum_e w_out[o][h*32+e] * ctx[d][e].
// ---------------------------------------------------------------------------
__global__ __launch_bounds__(256)
void ctxwf_kernel(const float* __restrict__ w_out)
{
    __shared__ float ctx[DHEAD][DHEAD + 1];

    const int bh  = blockIdx.x;        // b*4 + h
    const int b   = bh >> 2;
    const int h   = bh & 3;
    const int tid = threadIdx.x;

    // stage 1: 1024 entries, 4 per thread; consecutive tids -> consecutive idx
#pragma unroll
    for (int t = 0; t < 4; t++) {
        const int idx = tid + t * 256;           // d*32 + e
        const int d   = idx >> 5;
        const int e   = idx & 31;
        float s = 0.f;
#pragma unroll
        for (int c = 0; c < 32; c++)
            s += g_ctx_part[(long)c * 65536 + (long)bh * 1024 + idx];
        ctx[d][e] = s * g_kinv[bh * DHEAD + d];
    }
    __syncthreads();

    // stage 2: thread (d = tid&31, og = tid>>5) computes o = og*32 .. og*32+31
    const int d  = tid & 31;
    const int og = tid >> 5;
    for (int oo = 0; oo < 32; oo++) {
        const int o = og * 32 + oo;
        const float* wrow = w_out + o * INNER + h * DHEAD;   // warp-broadcast
        float s = 0.f;
#pragma unroll
        for (int e = 0; e < DHEAD; e++) s += wrow[e] * ctx[d][e];
        g_wf[(long)b * (CHAN * INNER) + o * INNER + h * DHEAD + d] = s;
    }
}

// ---------------------------------------------------------------------------
// K6: finalize per-batch mean / rstd from 64 tile partials.
// ---------------------------------------------------------------------------
__global__ __launch_bounds__(64)
void finstats_kernel()
{
    __shared__ float s1[64], s2[64];
    const int b   = blockIdx.x;
    const int tid = threadIdx.x;
    s1[tid] = g_statpart[(b * 64 + tid) * 2 + 0];
    s2[tid] = g_statpart[(b * 64 + tid) * 2 + 1];
    __syncthreads();
    for (int s = 32; s > 0; s >>= 1) {
        if (tid < s) { s1[tid] += s1[tid + s]; s2[tid] += s2[tid + s]; }
        __syncthreads();
    }
    if (tid == 0) {
        const float invn = 1.0f / (float)(CHAN * NPIX);
        const float mean = s1[0] * invn;
        const float var  = s2[0] * invn - mean * mean;
        g_meanrstd[b * 2 + 0] = mean;
        g_meanrstd[b * 2 + 1] = rsqrtf(var + EPS_GN);
    }
}

// ---------------------------------------------------------------------------
// K7: normalize d_out in place: (x - mean)*rstd*gamma[c] + beta[c].
// float4 over 16*256*4096 elements.
// ---------------------------------------------------------------------------
__global__ __launch_bounds__(256)
void normalize_kernel(float* __restrict__ out,
                      const float* __restrict__ gamma,
                      const float* __restrict__ beta)
{
    const long e4  = (long)blockIdx.x * blockDim.x + threadIdx.x; // 0..4194303
    const long off = e4 * 4;
    const int b = (int)(off >> 20);
    const int c = (int)((off >> 12) & 255);
    const float m = g_meanrstd[b * 2 + 0];
    const float r = g_meanrstd[b * 2 + 1];
    const float g  = gamma[c] * r;
    const float bb = beta[c] - m * g;
    float4 v = ((float4*)out)[e4];
    v.x = v.x * g + bb;
    v.y = v.y * g + bb;
    v.z = v.z * g + bb;
    v.w = v.w * g + bb;
    ((float4*)out)[e4] = v;
}

// ---------------------------------------------------------------------------
extern "C" void kernel_launch(void* const* d_in, const int* in_sizes, int n_in,
                              void* d_out, int out_size)
{
    const float* x      = (const float*)d_in[0];   // [16,256,64,64]
    const float* w_qkv  = (const float*)d_in[1];   // [384,256]
    const float* w_out  = (const float*)d_in[2];   // [256,128]
    const float* b_out  = (const float*)d_in[3];   // [256]
    const float* gammap = (const float*)d_in[4];   // [256]
    const float* betap  = (const float*)d_in[5];   // [256]
    float* out = (float*)d_out;

    float *p_qkv, *p_wf, *p_statpart;
    cudaGetSymbolAddress((void**)&p_qkv,      g_qkv);
    cudaGetSymbolAddress((void**)&p_wf,       g_wf);
    cudaGetSymbolAddress((void**)&p_statpart, g_statpart);

    // K1: qkv = w_qkv @ x
    gemm_f32x2_kernel<false><<<dim3(32, 3, BATCH), 256>>>(
        w_qkv, x, p_qkv,
        /*K=*/CHAN, /*lda=*/CHAN, /*ldb=*/NPIX, /*ldc=*/NPIX,
        /*aStride=*/0, /*bStride=*/(long)CHAN * NPIX, /*cStride=*/(long)O3 * NPIX,
        nullptr, nullptr, 0);

    // K2: q softmax + k stats (fused, disjoint data)
    qsm_kstats_kernel<<<3072, 256>>>();

    // K3: partial context
    ctx_part_kernel<<<dim3(32, 64), 128>>>();

    // K4: reduce ctx + build fused output-projection weights
    ctxwf_kernel<<<64, 256>>>(w_out);

    // K5: out = Wf @ q + b_out, with per-tile stats
    gemm_f32x2_kernel<true><<<dim3(32, 2, BATCH), 256>>>(
        p_wf, p_qkv, out,
        /*K=*/INNER, /*lda=*/INNER, /*ldb=*/NPIX, /*ldc=*/NPIX,
        /*aStride=*/(long)CHAN * INNER, /*bStride=*/(long)O3 * NPIX,
        /*cStride=*/(long)CHAN * NPIX,
        b_out, p_statpart, 64);

    // K6 + K7: per-sample normalization
    finstats_kernel<<<BATCH, 64>>>();
    normalize_kernel<<<16384, 256>>>(out, gammap, betap);
}

// round 11
// speedup vs baseline: 1.0612x; 1.0612x over previous
#include <cuda_runtime.h>
#include <cuda_bf16.h>

// ---------------------------------------------------------------------------
// ConvLinearAttention fused pipeline, fp32 + packed f32x2 FFMA GEMMs.
//   B=16, C=256, H*W=4096, HEADS=4, DIM_HEAD=32, inner=128
// Pipeline (7 launches):
//   K1: qkv = w_qkv @ x            (GEMM, per batch [384x256]@[256x4096])
//   K2: fused: q softmax over d * SCALE (blocks 0..1023)
//            + k row stats max/1/sum(exp) (blocks 1024..3071)
//   K3: partial context  ctx[d,e] += exp(k[d,n]-max_d) * v[e,n]
//       (8 chunks of 512 n; 4 sub-chunks of 128 accumulated in registers)
//   K4: fused: reduce 8 ctx chunks (apply 1/sum_d) in smem, stage w_out
//       slice in smem, then Wf[b][o][h*32+d] = sum_e w_out[o][h*32+e]*ctx[d][e]
//   K5: out = Wf[b] @ q + b_out    (GEMM [256x128]@[128x4096]) + per-tile
//       sum/sumsq partials for the per-sample norm
//   K6: finalize mean / rstd per batch
//   K7: out = (out - mean)*rstd*gamma[c] + beta[c]   (in place on d_out)
// GEMM: double-buffered smem (one barrier per k-tile) + register prefetch.
// R10 profile: ctxwf was 33.4us, occ 12.6%, all pipes <7% -> latency-starved;
// this round cuts its global-load count 4x and moves w_out reads to smem.
// ---------------------------------------------------------------------------

#define BATCH   16
#define CHAN    256
#define NPIX    4096
#define O3      384
#define INNER   128
#define HEADS   4
#define DHEAD   32
#define NCHUNK  8                      // context partial chunks (512 n each)
#define SCALE_Q 0.17677669529663687f   // 32^-0.5
#define EPS_GN  1e-5f

typedef unsigned long long ULL;

// ---- scratch (device globals: allocation-free) ----------------------------
__device__ float g_qkv[BATCH * O3 * NPIX];          // 96 MB
__device__ float g_kmax[BATCH * HEADS * DHEAD];     // 2048
__device__ float g_kinv[BATCH * HEADS * DHEAD];     // 2048
__device__ float g_ctx_part[NCHUNK * 64 * 1024];    // 2 MB  [chunk][bh][d*32+e]
__device__ float g_wf[BATCH * CHAN * INNER];        // 2 MB
__device__ float g_statpart[BATCH * 64 * 2];        // per-tile {sum, sumsq}
__device__ float g_meanrstd[BATCH * 2];             // {mean, rstd}

// ---- packed f32x2 helpers --------------------------------------------------
__device__ __forceinline__ ULL pack2(float x) {
    ULL r;
    asm("mov.b64 %0, {%1, %1};" : "=l"(r) : "f"(x));
    return r;
}
__device__ __forceinline__ void ffma2(ULL& d, ULL a, ULL b, ULL c) {
    asm("fma.rn.f32x2 %0, %1, %2, %3;" : "=l"(d) : "l"(a), "l"(b), "l"(c));
}
__device__ __forceinline__ float2 unpack2(ULL v) {
    float2 f;
    asm("mov.b64 {%0, %1}, %2;" : "=f"(f.x), "=f"(f.y) : "l"(v));
    return f;
}

// ---------------------------------------------------------------------------
// Tiled GEMM: C[b] = A[b] (MxK) @ Bm[b] (KxN), 128x128 tile, BK=16,
// 256 threads, 8m x (4+4)n per thread, packed fma.rn.f32x2 accumulation.
// Double-buffered smem: one __syncthreads per k-tile.
// FUSE: adds bias[row] and emits per-tile sum/sumsq partials.
// ---------------------------------------------------------------------------
template <bool FUSE>
__global__ __launch_bounds__(256, 2)
void gemm_f32x2_kernel(const float* __restrict__ A,
                       const float* __restrict__ Bm,
                       float* __restrict__ Cm,
                       int K, int lda, int ldb, int ldc,
                       long aStride, long bStride, long cStride,
                       const float* __restrict__ bias,
                       float* __restrict__ statPart,
                       int tilesPerBatch)
{
    __shared__ float As[2][16][132];   // [buf][k][m], padded
    __shared__ float Bs[2][16][128];   // [buf][k][n]

    const int b  = blockIdx.z;
    const float* Ab = A  + (long)b * aStride;
    const float* Bb = Bm + (long)b * bStride;
    float*       Cb = Cm + (long)b * cStride;

    const int m0  = blockIdx.y * 128;
    const int n0  = blockIdx.x * 128;
    const int tid = threadIdx.x;
    const int tx  = tid & 15;        // n-tile coord
    const int ty  = tid >> 4;        // m-tile coord

    ULL acc[8][4];
#pragma unroll
    for (int i = 0; i < 8; i++)
#pragma unroll
        for (int j = 0; j < 4; j++) acc[i][j] = 0ull;

    const int ar = tid >> 2;          // 0..63
    const int ac = (tid & 3) * 4;     // 0,4,8,12
    const int bk = tid >> 5;          // 0..7
    const int bn = (tid & 31) * 4;    // 0..124

    const float* aPtr0 = Ab + (long)(m0 + ar)      * lda + ac;
    const float* aPtr1 = Ab + (long)(m0 + ar + 64) * lda + ac;
    const float* bPtr0 = Bb + (long)bk       * ldb + n0 + bn;
    const float* bPtr1 = Bb + (long)(bk + 8) * ldb + n0 + bn;

    // prologue: tile 0 -> buf 0
    float4 av0 = *(const float4*)(aPtr0);
    float4 av1 = *(const float4*)(aPtr1);
    float4 bv0 = *(const float4*)(bPtr0);
    float4 bv1 = *(const float4*)(bPtr1);
    As[0][ac + 0][ar]      = av0.x;  As[0][ac + 1][ar]      = av0.y;
    As[0][ac + 2][ar]      = av0.z;  As[0][ac + 3][ar]      = av0.w;
    As[0][ac + 0][ar + 64] = av1.x;  As[0][ac + 1][ar + 64] = av1.y;
    As[0][ac + 2][ar + 64] = av1.z;  As[0][ac + 3][ar + 64] = av1.w;
    *(float4*)&Bs[0][bk][bn]     = bv0;
    *(float4*)&Bs[0][bk + 8][bn] = bv1;

    // prefetch tile 1 into registers
    if (16 < K) {
        av0 = *(const float4*)(aPtr0 + 16);
        av1 = *(const float4*)(aPtr1 + 16);
        bv0 = *(const float4*)(bPtr0 + (long)16 * ldb);
        bv1 = *(const float4*)(bPtr1 + (long)16 * ldb);
    }
    __syncthreads();

    int buf = 0;
    for (int k0 = 0; k0 < K; k0 += 16) {
#pragma unroll
        for (int k = 0; k < 16; k++) {
            const float4 a0 = *(const float4*)&As[buf][k][ty * 8];
            const float4 a1 = *(const float4*)&As[buf][k][ty * 8 + 4];
            // conflict-free: quarter-warp phase reads consecutive float4s
            const ulonglong2 bq0 = *(const ulonglong2*)&Bs[buf][k][tx * 4];      // n: tx*4+{0..3}
            const ulonglong2 bq1 = *(const ulonglong2*)&Bs[buf][k][64 + tx * 4]; // n: 64+tx*4+{0..3}
            ULL ap;
            ap = pack2(a0.x);
            ffma2(acc[0][0], ap, bq0.x, acc[0][0]);
            ffma2(acc[0][1], ap, bq0.y, acc[0][1]);
            ffma2(acc[0][2], ap, bq1.x, acc[0][2]);
            ffma2(acc[0][3], ap, bq1.y, acc[0][3]);
            ap = pack2(a0.y);
            ffma2(acc[1][0], ap, bq0.x, acc[1][0]);
            ffma2(acc[1][1], ap, bq0.y, acc[1][1]);
            ffma2(acc[1][2], ap, bq1.x, acc[1][2]);
            ffma2(acc[1][3], ap, bq1.y, acc[1][3]);
            ap = pack2(a0.z);
            ffma2(acc[2][0], ap, bq0.x, acc[2][0]);
            ffma2(acc[2][1], ap, bq0.y, acc[2][1]);
            ffma2(acc[2][2], ap, bq1.x, acc[2][2]);
            ffma2(acc[2][3], ap, bq1.y, acc[2][3]);
            ap = pack2(a0.w);
            ffma2(acc[3][0], ap, bq0.x, acc[3][0]);
            ffma2(acc[3][1], ap, bq0.y, acc[3][1]);
            ffma2(acc[3][2], ap, bq1.x, acc[3][2]);
            ffma2(acc[3][3], ap, bq1.y, acc[3][3]);
            ap = pack2(a1.x);
            ffma2(acc[4][0], ap, bq0.x, acc[4][0]);
            ffma2(acc[4][1], ap, bq0.y, acc[4][1]);
            ffma2(acc[4][2], ap, bq1.x, acc[4][2]);
            ffma2(acc[4][3], ap, bq1.y, acc[4][3]);
            ap = pack2(a1.y);
            ffma2(acc[5][0], ap, bq0.x, acc[5][0]);
            ffma2(acc[5][1], ap, bq0.y, acc[5][1]);
            ffma2(acc[5][2], ap, bq1.x, acc[5][2]);
            ffma2(acc[5][3], ap, bq1.y, acc[5][3]);
            ap = pack2(a1.z);
            ffma2(acc[6][0], ap, bq0.x, acc[6][0]);
            ffma2(acc[6][1], ap, bq0.y, acc[6][1]);
            ffma2(acc[6][2], ap, bq1.x, acc[6][2]);
            ffma2(acc[6][3], ap, bq1.y, acc[6][3]);
            ap = pack2(a1.w);
            ffma2(acc[7][0], ap, bq0.x, acc[7][0]);
            ffma2(acc[7][1], ap, bq0.y, acc[7][1]);
            ffma2(acc[7][2], ap, bq1.x, acc[7][2]);
            ffma2(acc[7][3], ap, bq1.y, acc[7][3]);
        }

        if (k0 + 16 < K) {
            // store prefetched tile k0+16 into the other buffer
            const int nb = buf ^ 1;
            As[nb][ac + 0][ar]      = av0.x;  As[nb][ac + 1][ar]      = av0.y;
            As[nb][ac + 2][ar]      = av0.z;  As[nb][ac + 3][ar]      = av0.w;
            As[nb][ac + 0][ar + 64] = av1.x;  As[nb][ac + 1][ar + 64] = av1.y;
            As[nb][ac + 2][ar + 64] = av1.z;  As[nb][ac + 3][ar + 64] = av1.w;
            *(float4*)&Bs[nb][bk][bn]     = bv0;
            *(float4*)&Bs[nb][bk + 8][bn] = bv1;
            __syncthreads();
            buf = nb;
            // prefetch tile k0+32 into registers (overlaps next compute)
            if (k0 + 32 < K) {
                av0 = *(const float4*)(aPtr0 + k0 + 32);
                av1 = *(const float4*)(aPtr1 + k0 + 32);
                bv0 = *(const float4*)(bPtr0 + (long)(k0 + 32) * ldb);
                bv1 = *(const float4*)(bPtr1 + (long)(k0 + 32) * ldb);
            }
        }
    }

    // ---- epilogue -----------------------------------------------------------
    float lsum = 0.f, lsq = 0.f;
#pragma unroll
    for (int i = 0; i < 8; i++) {
        const int row = m0 + ty * 8 + i;
        float bv = 0.f;
        if (FUSE) bv = bias[row];
        float out[8];
        float2 p;
        p = unpack2(acc[i][0]); out[0] = p.x + bv; out[1] = p.y + bv;
        p = unpack2(acc[i][1]); out[2] = p.x + bv; out[3] = p.y + bv;
        p = unpack2(acc[i][2]); out[4] = p.x + bv; out[5] = p.y + bv;
        p = unpack2(acc[i][3]); out[6] = p.x + bv; out[7] = p.y + bv;
        if (FUSE) {
#pragma unroll
            for (int j = 0; j < 8; j++) { lsum += out[j]; lsq += out[j] * out[j]; }
        }
        float* crow = Cb + (long)row * ldc + n0;
        *(float4*)(crow + tx * 4)      = make_float4(out[0], out[1], out[2], out[3]);
        *(float4*)(crow + 64 + tx * 4) = make_float4(out[4], out[5], out[6], out[7]);
    }

    if (FUSE) {
        float* rs = &As[0][0][0];  // reuse smem: 512 floats
        __syncthreads();           // all compute reads of smem done
        rs[tid]       = lsum;
        rs[256 + tid] = lsq;
        __syncthreads();
#pragma unroll
        for (int s = 128; s > 0; s >>= 1) {
            if (tid < s) {
                rs[tid]       += rs[tid + s];
                rs[256 + tid] += rs[256 + tid + s];
            }
            __syncthreads();
        }
        if (tid == 0) {
            const int tileIdx = blockIdx.y * gridDim.x + blockIdx.x;
            statPart[((long)b * tilesPerBatch + tileIdx) * 2 + 0] = rs[0];
            statPart[((long)b * tilesPerBatch + tileIdx) * 2 + 1] = rs[256];
        }
    }
}

// ---------------------------------------------------------------------------
// K2 (fused): blocks 0..1023  -> q softmax over d (*SCALE), in place.
//             blocks 1024..3071 -> k row stats: max over n, 1/sum(exp(k-max)).
// ---------------------------------------------------------------------------
__global__ __launch_bounds__(256)
void qsm_kstats_kernel()
{
    __shared__ float sm[256];
    const int tid = threadIdx.x;

    if (blockIdx.x < 1024) {
        // ---- q softmax: one thread per (b,h,n) ----
        const int idx = blockIdx.x * 256 + tid;                  // 0 .. 262143
        const int n  = idx & (NPIX - 1);
        const int bh = idx >> 12;                                // 0..63
        const int b  = bh >> 2;
        const int h  = bh & 3;
        float* base = g_qkv + ((long)b * O3 + h * DHEAD) * NPIX + n;

        float v[DHEAD];
        float mx = -3.0e38f;
#pragma unroll
        for (int d = 0; d < DHEAD; d++) {
            v[d] = base[(long)d * NPIX];
            mx = fmaxf(mx, v[d]);
        }
        float s = 0.f;
#pragma unroll
        for (int d = 0; d < DHEAD; d++) {
            v[d] = __expf(v[d] - mx);
            s += v[d];
        }
        const float inv = SCALE_Q / s;
#pragma unroll
        for (int d = 0; d < DHEAD; d++) base[(long)d * NPIX] = v[d] * inv;
    } else {
        // ---- k stats: one block per (b,hd) row ----
        const int row = blockIdx.x - 1024;          // b*128 + hd
        const int b   = row >> 7;
        const int hd  = row & 127;
        const float* p = g_qkv + ((long)b * O3 + INNER + hd) * NPIX;

        float mx = -3.0e38f;
#pragma unroll 4
        for (int i = tid * 4; i < NPIX; i += 256 * 4) {
            const float4 v = *(const float4*)(p + i);
            mx = fmaxf(mx, fmaxf(fmaxf(v.x, v.y), fmaxf(v.z, v.w)));
        }
        sm[tid] = mx;
        __syncthreads();
        for (int s = 128; s > 0; s >>= 1) {
            if (tid < s) sm[tid] = fmaxf(sm[tid], sm[tid + s]);
            __syncthreads();
        }
        mx = sm[0];
        __syncthreads();

        float acc = 0.f;
#pragma unroll 4
        for (int i = tid * 4; i < NPIX; i += 256 * 4) {
            const float4 v = *(const float4*)(p + i);
            acc += __expf(v.x - mx) + __expf(v.y - mx) + __expf(v.z - mx) + __expf(v.w - mx);
        }
        sm[tid] = acc;
        __syncthreads();
        for (int s = 128; s > 0; s >>= 1) {
            if (tid < s) sm[tid] += sm[tid + s];
            __syncthreads();
        }
        if (tid == 0) {
            g_kmax[row] = mx;
            g_kinv[row] = 1.0f / sm[0];
        }
    }
}

// ---------------------------------------------------------------------------
// K3: partial context. grid = (NCHUNK=8, bh=64), 128 threads.
// Each block loops 4 n-sub-chunks of 128 columns, staging exp(k - max) and v
// transposed in smem; thread (d = tid&31, eb = (tid>>5)*8) keeps 8 register
// accumulators across sub-chunks and writes ONE partial per chunk.
// ---------------------------------------------------------------------------
__global__ __launch_bounds__(128)
void ctx_part_kernel()
{
    __shared__ float keT[128][33];
    __shared__ float vsT[128][33];

    const int chunk = blockIdx.x;      // 0..7  (512 n each)
    const int bh    = blockIdx.y;      // 0..63
    const int b = bh >> 2, h = bh & 3;
    const int tid = threadIdx.x;
    const int d  = tid & 31;
    const int eb = (tid >> 5) * 8;

    float acc[8] = {0, 0, 0, 0, 0, 0, 0, 0};

    for (int sub = 0; sub < 4; sub++) {
        const int nbase = (chunk * 4 + sub) * 128;
        const float* kbase = g_qkv + ((long)b * O3 + INNER     + h * DHEAD) * NPIX + nbase;
        const float* vbase = g_qkv + ((long)b * O3 + 2 * INNER + h * DHEAD) * NPIX + nbase;

        if (sub > 0) __syncthreads();   // previous sub-chunk's reads done
#pragma unroll
        for (int i = 0; i < 8; i++) {
            const int idx = tid + i * 128;
            const int r  = idx >> 5;             // 0..31 (d/e row)
            const int c  = (idx & 31) * 4;       // 0..124
            const float mx = g_kmax[bh * DHEAD + r];
            const float4 kv = *(const float4*)(kbase + (long)r * NPIX + c);
            keT[c + 0][r] = __expf(kv.x - mx);
            keT[c + 1][r] = __expf(kv.y - mx);
            keT[c + 2][r] = __expf(kv.z - mx);
            keT[c + 3][r] = __expf(kv.w - mx);
            const float4 vv = *(const float4*)(vbase + (long)r * NPIX + c);
            vsT[c + 0][r] = vv.x;
            vsT[c + 1][r] = vv.y;
            vsT[c + 2][r] = vv.z;
            vsT[c + 3][r] = vv.w;
        }
        __syncthreads();

#pragma unroll 4
        for (int n = 0; n < 128; n++) {
            const float kd = keT[n][d];
#pragma unroll
            for (int i = 0; i < 8; i++) acc[i] += kd * vsT[n][eb + i];
        }
    }

    float* out = g_ctx_part + ((long)chunk * 64 + bh) * 1024 + d * 32 + eb;
#pragma unroll
    for (int i = 0; i < 8; i++) out[i] = acc[i];
}

// ---------------------------------------------------------------------------
// K4 (fused): per (b,h) block (64 blocks, 256 threads):
//   stage 0: stage w_out[:, h*32 : h*32+32] (256x32) into smem;
//   stage 1: reduce g_ctx_part over NCHUNK=8 chunks into smem ctx[32][33],
//            applying 1/sum_d;
//   stage 2: Wf[b][o][h*32+d] = sum_e ws[o][e] * ctx[d][e]  (all smem reads,
//            warp-broadcast on ws rows).
// ---------------------------------------------------------------------------
__global__ __launch_bounds__(256)
void ctxwf_kernel(const float* __restrict__ w_out)
{
    __shared__ float ctx[DHEAD][DHEAD + 1];
    __shared__ float ws[CHAN][DHEAD + 1];   // 33 KB

    const int bh  = blockIdx.x;        // b*4 + h
    const int b   = bh >> 2;
    const int h   = bh & 3;
    const int tid = threadIdx.x;

    // stage 0: stage w_out slice (coalesced 128B row segments)
#pragma unroll
    for (int t = 0; t < 32; t++) {
        const int i   = tid + t * 256;         // 0..8191
        const int row = i >> 5;                // 0..255
        const int col = i & 31;                // 0..31
        ws[row][col] = w_out[row * INNER + h * DHEAD + col];
    }

    // stage 1: 1024 entries, 4 per thread; consecutive tids -> consecutive idx
#pragma unroll
    for (int t = 0; t < 4; t++) {
        const int idx = tid + t * 256;           // d*32 + e
        const int d   = idx >> 5;
        const int e   = idx & 31;
        float s = 0.f;
#pragma unroll
        for (int c = 0; c < NCHUNK; c++)
            s += g_ctx_part[(long)c * 65536 + (long)bh * 1024 + idx];
        ctx[d][e] = s * g_kinv[bh * DHEAD + d];
    }
    __syncthreads();

    // stage 2: thread (d = tid&31, og = tid>>5) computes o = og*32 .. og*32+31
    const int d  = tid & 31;
    const int og = tid >> 5;
    for (int oo = 0; oo < 32; oo++) {
        const int o = og * 32 + oo;
        float s = 0.f;
#pragma unroll
        for (int e = 0; e < DHEAD; e++) s += ws[o][e] * ctx[d][e];
        g_wf[(long)b * (CHAN * INNER) + o * INNER + h * DHEAD + d] = s;
    }
}

// ---------------------------------------------------------------------------
// K6: finalize per-batch mean / rstd from 64 tile partials.
// ---------------------------------------------------------------------------
__global__ __launch_bounds__(64)
void finstats_kernel()
{
    __shared__ float s1[64], s2[64];
    const int b   = blockIdx.x;
    const int tid = threadIdx.x;
    s1[tid] = g_statpart[(b * 64 + tid) * 2 + 0];
    s2[tid] = g_statpart[(b * 64 + tid) * 2 + 1];
    __syncthreads();
    for (int s = 32; s > 0; s >>= 1) {
        if (tid < s) { s1[tid] += s1[tid + s]; s2[tid] += s2[tid + s]; }
        __syncthreads();
    }
    if (tid == 0) {
        const float invn = 1.0f / (float)(CHAN * NPIX);
        const float mean = s1[0] * invn;
        const float var  = s2[0] * invn - mean * mean;
        g_meanrstd[b * 2 + 0] = mean;
        g_meanrstd[b * 2 + 1] = rsqrtf(var + EPS_GN);
    }
}

// ---------------------------------------------------------------------------
// K7: normalize d_out in place: (x - mean)*rstd*gamma[c] + beta[c].
// ---------------------------------------------------------------------------
__global__ __launch_bounds__(256)
void normalize_kernel(float* __restrict__ out,
                      const float* __restrict__ gamma,
                      const float* __restrict__ beta)
{
    const long e4  = (long)blockIdx.x * blockDim.x + threadIdx.x; // 0..4194303
    const long off = e4 * 4;
    const int b = (int)(off >> 20);
    const int c = (int)((off >> 12) & 255);
    const float m = g_meanrstd[b * 2 + 0];
    const float r = g_meanrstd[b * 2 + 1];
    const float g  = gamma[c] * r;
    const float bb = beta[c] - m * g;
    float4 v = ((float4*)out)[e4];
    v.x = v.x * g + bb;
    v.y = v.y * g + bb;
    v.z = v.z * g + bb;
    v.w = v.w * g + bb;
    ((float4*)out)[e4] = v;
}

// ---------------------------------------------------------------------------
extern "C" void kernel_launch(void* const* d_in, const int* in_sizes, int n_in,
                              void* d_out, int out_size)
{
    const float* x      = (const float*)d_in[0];   // [16,256,64,64]
    const float* w_qkv  = (const float*)d_in[1];   // [384,256]
    const float* w_out  = (const float*)d_in[2];   // [256,128]
    const float* b_out  = (const float*)d_in[3];   // [256]
    const float* gammap = (const float*)d_in[4];   // [256]
    const float* betap  = (const float*)d_in[5];   // [256]
    float* out = (float*)d_out;

    float *p_qkv, *p_wf, *p_statpart;
    cudaGetSymbolAddress((void**)&p_qkv,      g_qkv);
    cudaGetSymbolAddress((void**)&p_wf,       g_wf);
    cudaGetSymbolAddress((void**)&p_statpart, g_statpart);

    // K1: qkv = w_qkv @ x
    gemm_f32x2_kernel<false><<<dim3(32, 3, BATCH), 256>>>(
        w_qkv, x, p_qkv,
        /*K=*/CHAN, /*lda=*/CHAN, /*ldb=*/NPIX, /*ldc=*/NPIX,
        /*aStride=*/0, /*bStride=*/(long)CHAN * NPIX, /*cStride=*/(long)O3 * NPIX,
        nullptr, nullptr, 0);

    // K2: q softmax + k stats (fused, disjoint data)
    qsm_kstats_kernel<<<3072, 256>>>();

    // K3: partial context (8 chunks, register accumulation over 4 sub-chunks)
    ctx_part_kernel<<<dim3(NCHUNK, 64), 128>>>();

    // K4: reduce ctx + build fused output-projection weights
    ctxwf_kernel<<<64, 256>>>(w_out);

    // K5: out = Wf @ q + b_out, with per-tile stats
    gemm_f32x2_kernel<true><<<dim3(32, 2, BATCH), 256>>>(
        p_wf, p_qkv, out,
        /*K=*/INNER, /*lda=*/INNER, /*ldb=*/NPIX, /*ldc=*/NPIX,
        /*aStride=*/(long)CHAN * INNER, /*bStride=*/(long)O3 * NPIX,
        /*cStride=*/(long)CHAN * NPIX,
        b_out, p_statpart, 64);

    // K6 + K7: per-sample normalization
    finstats_kernel<<<BATCH, 64>>>();
    normalize_kernel<<<16384, 256>>>(out, gammap, betap);
}